// round 13
// baseline (speedup 1.0000x reference)
#include <cuda_runtime.h>
#include <cuda_fp16.h>
#include <cstdint>

typedef __half h16;

#define TT 4
#define NN 8192
#define HD 256
#define RPAD 8320        // 1 zero halo row + 8192 data + tail pad (zero)
#define KT 256           // single fp16 term: K = 256
#define BM 128
#define BN 128
#define BK 64
#define NCH 4            // 256/64
#define MV 126           // valid output rows per M-tile
#define MT 66            // ceil(8192/126)
#define PSTRIDE 130
#define NTHR 128
#define NPERSIST 296     // 2 CTAs x 148 SMs
#define SMEM_BYTES (BM*PSTRIDE*4)            // 66560 (P tile; aliases stages)
#define STAGE_BYTES ((BM*BK + BN*BK)*2)      // 32768
#define A_STAGE_BYTES (BM*BK*2)              // 16384

// ------------------- device scratch (zero-initialized at load) -------------
__device__ __align__(256) h16 g_X[(size_t)TT*RPAD*HD];
__device__ __align__(256) h16 g_A[(size_t)TT*RPAD*HD];
__device__ __align__(256) h16 g_B[(size_t)TT*RPAD*HD];
__device__ __align__(256) h16 g_W1[HD*KT];
__device__ __align__(256) h16 g_WL[(size_t)8*2048*KT];
__device__ float g_bcat[8*2048];
__device__ float g_tw[10];
__device__ float g_aw[3];
__device__ float g_psum[HD];
__device__ float g_pmax[HD];

// ------------------- PTX helpers -------------------------------------------
__device__ __forceinline__ void cp_async16(unsigned dst, const void* src) {
    asm volatile("cp.async.cg.shared.global [%0], [%1], 16;\n" :: "r"(dst), "l"(src));
}
__device__ __forceinline__ void cp_commit() {
    asm volatile("cp.async.commit_group;\n" ::);
}
template <int N>
__device__ __forceinline__ void cp_wait() {
    asm volatile("cp.async.wait_group %0;\n" :: "n"(N));
}
__device__ __forceinline__ void ldsm4(unsigned addr, unsigned& r0, unsigned& r1,
                                      unsigned& r2, unsigned& r3) {
    asm volatile("ldmatrix.sync.aligned.m8n8.x4.shared.b16 {%0,%1,%2,%3}, [%4];\n"
                 : "=r"(r0), "=r"(r1), "=r"(r2), "=r"(r3) : "r"(addr));
}
__device__ __forceinline__ void mma16816(float c[4], const unsigned a[4], const unsigned b[2]) {
    asm volatile(
        "mma.sync.aligned.m16n8k16.row.col.f32.f16.f16.f32 "
        "{%0,%1,%2,%3}, {%4,%5,%6,%7}, {%8,%9}, {%0,%1,%2,%3};\n"
        : "+f"(c[0]), "+f"(c[1]), "+f"(c[2]), "+f"(c[3])
        : "r"(a[0]), "r"(a[1]), "r"(a[2]), "r"(a[3]), "r"(b[0]), "r"(b[1]));
}
__device__ __forceinline__ unsigned swz(unsigned b) { return b ^ ((b >> 3) & 0x70); }

__device__ __forceinline__ void atomicMaxFloat(float* addr, float val) {
    if (val >= 0.f) atomicMax((int*)addr, __float_as_int(val));
    else            atomicMin((unsigned int*)addr, (unsigned int)__float_as_int(val));
}

__device__ __forceinline__ h16* sel_buf(int s) { return s==0 ? g_X : (s==1 ? g_A : g_B); }

// ------------------- prep kernels ------------------------------------------
__global__ void k_packx(const float* __restrict__ x, const float* __restrict__ w1) {
    size_t gid = (size_t)blockIdx.x * blockDim.x + threadIdx.x;
    if (gid < 65536) {
        int n = (int)(gid >> 8), k = (int)(gid & 255);
        g_W1[n*KT + k] = __float2half(w1[k * HD + n]);  // lin1_w[k][n]
    }
    if (gid < 256) {
        g_psum[gid] = 0.f;
        g_pmax[gid] = -3.4e38f;
    }
    size_t total = (size_t)TT * RPAD * HD;
    for (size_t i = gid; i < total; i += (size_t)gridDim.x * blockDim.x) {
        int ch = (int)(i & 255);
        size_t row = i >> 8;                 // t*RPAD + p
        int p = (int)(row % RPAD);
        float v = 0.f;
        int n = p - 1;
        if (n >= 0 && n < NN) {
            int t = (int)(row / RPAD);
            v = x[((size_t)t * NN + n) * HD + ch];
        }
        g_X[i] = __float2half(v);
    }
}

__global__ void k_packwl(const float* __restrict__ lw,  const float* __restrict__ lb,
                         const float* __restrict__ rlw, const float* __restrict__ rlb,
                         const float* __restrict__ cw,  const float* __restrict__ cb,
                         const float* __restrict__ rcw, const float* __restrict__ rcb,
                         const float* __restrict__ ta,  const float* __restrict__ aa) {
    if (blockIdx.x == 0 && threadIdx.x == 0) {
        for (int l = 0; l < 2; l++) {
            float m = -1e30f;
            for (int i = 0; i < 5; i++) m = fmaxf(m, ta[l*5+i]);
            float e[5], s = 0.f;
            for (int i = 0; i < 5; i++) { e[i] = expf(ta[l*5+i] - m); s += e[i]; }
            for (int i = 0; i < 5; i++) g_tw[l*5+i] = e[i] / s;
        }
        float m = -1e30f;
        for (int i = 0; i < 3; i++) m = fmaxf(m, aa[i]);
        float e[3], s = 0.f;
        for (int i = 0; i < 3; i++) { e[i] = expf(aa[i] - m); s += e[i]; }
        for (int i = 0; i < 3; i++) g_aw[i] = e[i] / s;
    }
    size_t i = (size_t)blockIdx.x * blockDim.x + threadIdx.x;  // over 8*2048*256
    if (i >= (size_t)8 * 2048 * 256) return;
    int k  = (int)(i & 255);
    int n  = (int)((i >> 8) & 2047);
    int lt = (int)(i >> 19);         // 0..7
    int l = lt >> 2, t = lt & 3;
    int j = n >> 3, op = n & 7;
    float v;
    if (op == 0)      v = lw[(l*256 + k)*256 + j];
    else if (op == 1) v = rlw[((l*4 + t)*256 + k)*256 + j];
    else if (op < 5)  { int kk = op - 2; v = cw[((l*256 + j)*256 + k)*3 + kk]; }
    else              { int kk = op - 5; v = rcw[(((l*4 + t)*256 + j)*256 + k)*3 + kk]; }
    g_WL[((size_t)lt * 2048 + n) * KT + k] = __float2half(v);
    if (k == 0) {
        float b = 0.f;
        if (op == 0)      b = lb[l*256 + j];
        else if (op == 1) b = rlb[(l*4 + t)*256 + j];
        else if (op == 3) b = cb[l*256 + j];
        else if (op == 6) b = rcb[(l*4 + t)*256 + j];
        g_bcat[lt*2048 + n] = b;
    }
}

// ------------------- fused GEMM + epilogue (persistent) --------------------
// P[128 x 128] = A[128 x 256] * B[128 x 256]^T, fp16 operands, fp32 accumulate
// 128 threads, 4 warps, 64x64 warp tiles, 2 CTAs/SM, persistent over tiles.
// mode 0: lin1 (tile covers 128 channels);  NT = 2*4*66, TNC = 2
// mode 1: layer (16 channels x 8 op taps);  NT = 16*4*66, TNC = 16
//   layer==0: writes next activations.  layer==1: only aggregation (stores dead).
__global__ void __launch_bounds__(NTHR, 2)
k_gemm(int abuf, int obuf, const float* __restrict__ bias1, int mode, int layer,
       int ntiles, int tnc) {
    extern __shared__ char smem[];
    const int tid = threadIdx.x;
    const int wid = tid >> 5, lane = tid & 31;

    const h16* Abase = sel_buf(abuf);
    h16* Oh = sel_buf(obuf);
    unsigned sbase = (unsigned)__cvta_generic_to_shared(smem);
    float* P = (float*)smem;

    // warp tiling: wm in {0,1} -> 64 rows; wn in {0,1} -> 64 cols (tile-invariant)
    const int wm = wid & 1, wn = (wid >> 1) & 1;
    unsigned abase_[4], amask[4], bbase[4], bmask[4];
    const unsigned aK = (unsigned)((lane >> 4) * 16);        // bytes
    const unsigned bK = (unsigned)(((lane >> 3) & 1) * 16);  // bytes
    {
        int r = wm * 64 + ((lane >> 3) & 1) * 8 + (lane & 7);
#pragma unroll
        for (int mf = 0; mf < 4; mf++) {
            unsigned rb = (unsigned)((r + mf * 16) * 128);
            abase_[mf] = rb;
            amask[mf] = (rb >> 3) & 0x70;
        }
        int nr = wn * 64 + (lane >> 4) * 8 + (lane & 7);
#pragma unroll
        for (int fp = 0; fp < 4; fp++) {
            unsigned rb = (unsigned)((nr + fp * 16) * 128);
            bbase[fp] = rb;
            bmask[fp] = (rb >> 3) & 0x70;
        }
    }

#pragma unroll 1
    for (int tl = blockIdx.x; tl < ntiles; tl += NPERSIST) {
        // tm-major, (t, tn) inner: concurrent CTAs share B tiles in L2
        int tm  = tl / (tnc * TT);
        int rem = tl - tm * (tnc * TT);
        int t   = rem / tnc;
        int tn  = rem - t * tnc;

        const h16* Ah = Abase + (size_t)t * RPAD * HD;
        const h16* Bp = mode ? (g_WL + ((size_t)(layer*4 + t) * 2048 + (size_t)tn * BN) * KT)
                             : (g_W1 + (size_t)tn * BN * KT);
        const int row0 = tm * MV;

        float c[8][4][4];
#pragma unroll
        for (int a = 0; a < 8; a++)
#pragma unroll
            for (int b = 0; b < 4; b++)
#pragma unroll
                for (int i = 0; i < 4; i++) c[a][b][i] = 0.f;

        auto load_chunk = [&](int ck, int stage) {
            unsigned sA = sbase + stage * STAGE_BYTES;
            unsigned sB = sA + A_STAGE_BYTES;
            int kofs = ck * 64;
#pragma unroll
            for (int i = 0; i < 8; i++) {
                int idx = tid + i * NTHR;         // 0..1023
                int r = idx >> 3, cc = idx & 7;
                const h16* src = Ah + (size_t)(row0 + r) * HD + kofs + cc * 8;
                cp_async16(sA + swz((unsigned)(r * 128 + cc * 16)), src);
            }
#pragma unroll
            for (int i = 0; i < 8; i++) {
                int idx = tid + i * NTHR;         // 0..1023
                int r = idx >> 3, cc = idx & 7;
                const h16* src = Bp + (size_t)r * KT + kofs + cc * 8;
                cp_async16(sB + swz((unsigned)(r * 128 + cc * 16)), src);
            }
            cp_commit();
        };

        auto compute_chunk = [&](int stage) {
            unsigned sA = sbase + stage * STAGE_BYTES;
            unsigned sB = sA + A_STAGE_BYTES;
#pragma unroll
            for (int ks = 0; ks < 4; ks++) {
                unsigned a[4][4];
#pragma unroll
                for (int mf = 0; mf < 4; mf++) {
                    unsigned addr = sA + abase_[mf] + (((unsigned)(ks * 32) + aK) ^ amask[mf]);
                    ldsm4(addr, a[mf][0], a[mf][1], a[mf][2], a[mf][3]);
                }
                unsigned b[8][2];
#pragma unroll
                for (int fp = 0; fp < 4; fp++) {
                    unsigned addr = sB + bbase[fp] + (((unsigned)(ks * 32) + bK) ^ bmask[fp]);
                    ldsm4(addr, b[2*fp][0], b[2*fp][1], b[2*fp+1][0], b[2*fp+1][1]);
                }
#pragma unroll
                for (int nf = 0; nf < 8; nf++)
#pragma unroll
                    for (int mf = 0; mf < 4; mf++)
                        mma16816(c[nf][mf], a[mf], b[nf]);
            }
        };

        load_chunk(0, 0);
#pragma unroll 1
        for (int ck = 0; ck < NCH; ck++) {
            if (ck + 1 < NCH) { load_chunk(ck + 1, (ck + 1) & 1); cp_wait<1>(); }
            else              { cp_wait<0>(); }
            __syncthreads();
            compute_chunk(ck & 1);
            __syncthreads();
        }

        // ---- prefetch identity term (independent of P) before smem turnover
        float hold[16];
        if (mode == 1) {
#pragma unroll
            for (int i = 0; i < 16; i++) {
                int idx = tid + i * NTHR;
                if (idx < MV * 16) {
                    int r = (idx >> 4) + 1;
                    int jg = tn * 16 + (idx & 15);
                    hold[i] = __half2float(Ah[(size_t)(row0 + r) * HD + jg]);
                }
            }
        }

        // ---- write accumulators to smem P tile (aliases stage buffers) ----
        {
            int rbase = wm * 64 + (lane >> 2);
            int cbase = wn * 64 + (lane & 3) * 2;
#pragma unroll
            for (int nf = 0; nf < 8; nf++) {
#pragma unroll
                for (int mf = 0; mf < 4; mf++) {
                    int col = cbase + nf * 8;
                    int rr = rbase + mf * 16;
                    *(float2*)&P[rr * PSTRIDE + col]       = make_float2(c[nf][mf][0], c[nf][mf][1]);
                    *(float2*)&P[(rr + 8) * PSTRIDE + col] = make_float2(c[nf][mf][2], c[nf][mf][3]);
                }
            }
        }
        __syncthreads();

        if (mode == 0) {
            for (int idx = tid; idx < MV * BN; idx += NTHR) {
                int r = (idx >> 7) + 1;
                int chl = idx & 127;
                int node = row0 + r - 1;
                if (node >= NN) continue;
                int ch = tn * BN + chl;
                float h = P[r * PSTRIDE + chl] + bias1[ch];
                size_t o = (size_t)t * RPAD * HD + (size_t)(node + 1) * HD + ch;
                Oh[o] = __float2half(h);
            }
        } else {
            const float w0 = g_tw[layer*5+0], w1 = g_tw[layer*5+1], w2 = g_tw[layer*5+2],
                        w3 = g_tw[layer*5+3], w4 = g_tw[layer*5+4];
            const float* bc = g_bcat + (layer*4 + t) * 2048 + tn * BN;
            float accS = 0.f, accM = -3.4e38f;
#pragma unroll
            for (int i = 0; i < 16; i++) {
                int idx = tid + i * NTHR;
                if (idx >= MV * 16) break;
                int r = (idx >> 4) + 1;
                int jc = idx & 15;
                int node = row0 + r - 1;
                if (node >= NN) continue;
                int col = jc * 8;
                const float* Pr = P + r * PSTRIDE;
                float plin = Pr[col + 0];
                float prl  = Pr[col + 1];
                float pc   = Pr[col + 2 - PSTRIDE] + Pr[col + 3] + Pr[col + 4 + PSTRIDE];
                float prc  = Pr[col + 5 - PSTRIDE] + Pr[col + 6] + Pr[col + 7 + PSTRIDE];
                float h = w0 * fmaxf(plin + bc[col + 0], 0.f)
                        + w1 * fmaxf(prl  + bc[col + 1], 0.f)
                        + w2 * fmaxf(pc   + bc[col + 3], 0.f)
                        + w3 * fmaxf(prc  + bc[col + 6], 0.f)
                        + w4 * hold[i];
                if (layer == 0) {
                    int jg = tn * 16 + jc;
                    size_t o = (size_t)t * RPAD * HD + (size_t)(node + 1) * HD + jg;
                    Oh[o] = __float2half(h);
                } else {
                    accS += h; accM = fmaxf(accM, h);
                }
            }
            if (layer == 1) {
                __syncthreads();                 // everyone done reading P
                float* R = (float*)smem;         // reuse smem for reduction
                R[tid]        = accS;
                R[NTHR + tid] = accM;
                __syncthreads();
                if (tid < 16) {                  // tid == jc
                    float s = 0.f, m = -3.4e38f;
#pragma unroll
                    for (int g = 0; g < NTHR / 16; g++) {
                        s += R[g * 16 + tid];
                        m = fmaxf(m, R[NTHR + g * 16 + tid]);
                    }
                    int ch = tn * 16 + tid;
                    atomicAdd(&g_psum[ch], s);
                    atomicMaxFloat(&g_pmax[ch], m);
                }
            }
        }
        __syncthreads();   // protect P/stage smem before next tile's loads
    }
}

// ------------------- final head --------------------------------------------
__global__ void k_agg2(const float* __restrict__ ow, const float* __restrict__ ob,
                       float* __restrict__ out) {
    __shared__ float agg[HD];
    int j = threadIdx.x;
    float s  = g_psum[j];
    float mx = g_pmax[j];
    agg[j] = g_aw[0] * s + g_aw[1] * (s / 32768.f) + g_aw[2] * mx;
    __syncthreads();
    if (j < 64) {
        float acc = ob[j];
        for (int k = 0; k < HD; k++) acc += agg[k] * ow[k * 64 + j];
        out[j] = acc;
    }
}

// ------------------- launcher ----------------------------------------------
extern "C" void kernel_launch(void* const* d_in, const int* in_sizes, int n_in,
                              void* d_out, int out_size) {
    (void)in_sizes; (void)n_in; (void)out_size;
    const float* x          = (const float*)d_in[0];
    const float* lin1_w     = (const float*)d_in[1];
    const float* lin1_b     = (const float*)d_in[2];
    const float* lin_w      = (const float*)d_in[3];
    const float* lin_b      = (const float*)d_in[4];
    const float* rel_lin_w  = (const float*)d_in[5];
    const float* rel_lin_b  = (const float*)d_in[6];
    const float* conv_w     = (const float*)d_in[7];
    const float* conv_b     = (const float*)d_in[8];
    const float* rel_conv_w = (const float*)d_in[9];
    const float* rel_conv_b = (const float*)d_in[10];
    const float* out_w      = (const float*)d_in[11];
    const float* out_b      = (const float*)d_in[12];
    const float* trans_arch = (const float*)d_in[13];
    const float* agg_arch   = (const float*)d_in[14];
    float* out = (float*)d_out;

    cudaFuncSetAttribute(k_gemm, cudaFuncAttributeMaxDynamicSharedMemorySize, SMEM_BYTES);

    k_packx<<<4096, 256>>>(x, lin1_w);
    k_packwl<<<(8 * 2048 * 256 + 255) / 256, 256>>>(lin_w, lin_b, rel_lin_w, rel_lin_b,
                                                    conv_w, conv_b, rel_conv_w, rel_conv_b,
                                                    trans_arch, agg_arch);

    // lin1: X -> A  (tiles = 2*4*66 = 528, tnc = 2)
    k_gemm<<<NPERSIST, NTHR, SMEM_BYTES>>>(0, 1, lin1_b, 0, 0, 2 * TT * MT, 2);
    // layer 0: A -> B  (tiles = 16*4*66 = 4224, tnc = 16)
    k_gemm<<<NPERSIST, NTHR, SMEM_BYTES>>>(1, 2, nullptr, 1, 0, 16 * TT * MT, 16);
    // layer 1: B -> (aggregation only)
    k_gemm<<<NPERSIST, NTHR, SMEM_BYTES>>>(2, 1, nullptr, 1, 1, 16 * TT * MT, 16);

    k_agg2<<<1, 256>>>(out_w, out_b, out);
}

// round 15
// speedup vs baseline: 1.0967x; 1.0967x over previous
#include <cuda_runtime.h>
#include <cuda_fp16.h>
#include <cstdint>

typedef __half h16;

#define TT 4
#define NN 8192
#define HD 256
#define RPAD 8320        // 1 zero halo row + 8192 data + tail pad (zero)
#define KT 256           // single fp16 term: K = 256
#define BM 128
#define BN 128
#define BK 64
#define NCH 4            // 256/64
#define MV 126           // valid output rows per M-tile
#define MT 66            // ceil(8192/126)
#define PSTRIDE 130
#define NTHR 128
#define STAGE_BYTES ((BM*BK + BN*BK)*2)      // 32768
#define A_STAGE_BYTES (BM*BK*2)              // 16384
#define SMEM_BYTES (3*STAGE_BYTES)           // 98304 >= P tile 66560 (aliased)

// ------------------- device scratch (zero-initialized at load) -------------
__device__ __align__(256) h16 g_X[(size_t)TT*RPAD*HD];
__device__ __align__(256) h16 g_A[(size_t)TT*RPAD*HD];
__device__ __align__(256) h16 g_B[(size_t)TT*RPAD*HD];
__device__ __align__(256) h16 g_W1[HD*KT];
__device__ __align__(256) h16 g_WL[(size_t)8*2048*KT];
__device__ float g_bcat[8*2048];
__device__ float g_tw[10];
__device__ float g_aw[3];
__device__ float g_psum[HD];
__device__ float g_pmax[HD];

// ------------------- PTX helpers -------------------------------------------
__device__ __forceinline__ void cp_async16(unsigned dst, const void* src) {
    asm volatile("cp.async.cg.shared.global [%0], [%1], 16;\n" :: "r"(dst), "l"(src));
}
__device__ __forceinline__ void cp_commit() {
    asm volatile("cp.async.commit_group;\n" ::);
}
template <int N>
__device__ __forceinline__ void cp_wait() {
    asm volatile("cp.async.wait_group %0;\n" :: "n"(N));
}
__device__ __forceinline__ void ldsm4(unsigned addr, unsigned& r0, unsigned& r1,
                                      unsigned& r2, unsigned& r3) {
    asm volatile("ldmatrix.sync.aligned.m8n8.x4.shared.b16 {%0,%1,%2,%3}, [%4];\n"
                 : "=r"(r0), "=r"(r1), "=r"(r2), "=r"(r3) : "r"(addr));
}
__device__ __forceinline__ void mma16816(float c[4], const unsigned a[4], const unsigned b[2]) {
    asm volatile(
        "mma.sync.aligned.m16n8k16.row.col.f32.f16.f16.f32 "
        "{%0,%1,%2,%3}, {%4,%5,%6,%7}, {%8,%9}, {%0,%1,%2,%3};\n"
        : "+f"(c[0]), "+f"(c[1]), "+f"(c[2]), "+f"(c[3])
        : "r"(a[0]), "r"(a[1]), "r"(a[2]), "r"(a[3]), "r"(b[0]), "r"(b[1]));
}
__device__ __forceinline__ unsigned swz(unsigned b) { return b ^ ((b >> 3) & 0x70); }

__device__ __forceinline__ void atomicMaxFloat(float* addr, float val) {
    if (val >= 0.f) atomicMax((int*)addr, __float_as_int(val));
    else            atomicMin((unsigned int*)addr, (unsigned int)__float_as_int(val));
}

__device__ __forceinline__ h16* sel_buf(int s) { return s==0 ? g_X : (s==1 ? g_A : g_B); }

// ------------------- prep kernels ------------------------------------------
__global__ void k_packx(const float* __restrict__ x, const float* __restrict__ w1) {
    size_t gid = (size_t)blockIdx.x * blockDim.x + threadIdx.x;
    if (gid < 65536) {
        int n = (int)(gid >> 8), k = (int)(gid & 255);
        g_W1[n*KT + k] = __float2half(w1[k * HD + n]);  // lin1_w[k][n]
    }
    if (gid < 256) {
        g_psum[gid] = 0.f;
        g_pmax[gid] = -3.4e38f;
    }
    size_t total = (size_t)TT * RPAD * HD;
    for (size_t i = gid; i < total; i += (size_t)gridDim.x * blockDim.x) {
        int ch = (int)(i & 255);
        size_t row = i >> 8;                 // t*RPAD + p
        int p = (int)(row % RPAD);
        float v = 0.f;
        int n = p - 1;
        if (n >= 0 && n < NN) {
            int t = (int)(row / RPAD);
            v = x[((size_t)t * NN + n) * HD + ch];
        }
        g_X[i] = __float2half(v);
    }
}

__global__ void k_packwl(const float* __restrict__ lw,  const float* __restrict__ lb,
                         const float* __restrict__ rlw, const float* __restrict__ rlb,
                         const float* __restrict__ cw,  const float* __restrict__ cb,
                         const float* __restrict__ rcw, const float* __restrict__ rcb,
                         const float* __restrict__ ta,  const float* __restrict__ aa) {
    if (blockIdx.x == 0 && threadIdx.x == 0) {
        for (int l = 0; l < 2; l++) {
            float m = -1e30f;
            for (int i = 0; i < 5; i++) m = fmaxf(m, ta[l*5+i]);
            float e[5], s = 0.f;
            for (int i = 0; i < 5; i++) { e[i] = expf(ta[l*5+i] - m); s += e[i]; }
            for (int i = 0; i < 5; i++) g_tw[l*5+i] = e[i] / s;
        }
        float m = -1e30f;
        for (int i = 0; i < 3; i++) m = fmaxf(m, aa[i]);
        float e[3], s = 0.f;
        for (int i = 0; i < 3; i++) { e[i] = expf(aa[i] - m); s += e[i]; }
        for (int i = 0; i < 3; i++) g_aw[i] = e[i] / s;
    }
    size_t i = (size_t)blockIdx.x * blockDim.x + threadIdx.x;  // over 8*2048*256
    if (i >= (size_t)8 * 2048 * 256) return;
    int k  = (int)(i & 255);
    int n  = (int)((i >> 8) & 2047);
    int lt = (int)(i >> 19);         // 0..7
    int l = lt >> 2, t = lt & 3;
    int j = n >> 3, op = n & 7;
    float v;
    if (op == 0)      v = lw[(l*256 + k)*256 + j];
    else if (op == 1) v = rlw[((l*4 + t)*256 + k)*256 + j];
    else if (op < 5)  { int kk = op - 2; v = cw[((l*256 + j)*256 + k)*3 + kk]; }
    else              { int kk = op - 5; v = rcw[(((l*4 + t)*256 + j)*256 + k)*3 + kk]; }
    g_WL[((size_t)lt * 2048 + n) * KT + k] = __float2half(v);
    if (k == 0) {
        float b = 0.f;
        if (op == 0)      b = lb[l*256 + j];
        else if (op == 1) b = rlb[(l*4 + t)*256 + j];
        else if (op == 3) b = cb[l*256 + j];
        else if (op == 6) b = rcb[(l*4 + t)*256 + j];
        g_bcat[lt*2048 + n] = b;
    }
}

// ------------------- fused GEMM + epilogue ---------------------------------
// P[128 x 128] = A[128 x 256] * B[128 x 256]^T, fp16 operands, fp32 accumulate
// 128 threads, 4 warps, 64x64 warp tiles, 2 CTAs/SM.
// 3-stage cp.async pipeline: ONE __syncthreads per K-chunk (was two).
// mode 0: lin1.  mode 1: layer epilogue; layer==0 writes activations,
// layer==1 only aggregates (activation stores are dead).
__global__ void __launch_bounds__(NTHR, 2)
k_gemm(int abuf, int obuf, const float* __restrict__ bias1, int mode, int layer) {
    extern __shared__ char smem[];
    const int tid = threadIdx.x;
    const int wid = tid >> 5, lane = tid & 31;
    const int tn = blockIdx.x, tm = blockIdx.y, t = blockIdx.z;

    const h16* Ah = sel_buf(abuf) + (size_t)t * RPAD * HD;
    const h16* Bp = mode ? (g_WL + ((size_t)(layer*4 + t) * 2048 + (size_t)tn * BN) * KT)
                         : (g_W1 + (size_t)tn * BN * KT);
    h16* Oh = sel_buf(obuf);

    const int row0 = tm * MV;   // global padded row of A-tile row 0
    unsigned sbase = (unsigned)__cvta_generic_to_shared(smem);

    float c[8][4][4];
#pragma unroll
    for (int a = 0; a < 8; a++)
#pragma unroll
        for (int b = 0; b < 4; b++)
#pragma unroll
            for (int i = 0; i < 4; i++) c[a][b][i] = 0.f;

    auto load_chunk = [&](int ck, int stage) {
        unsigned sA = sbase + stage * STAGE_BYTES;
        unsigned sB = sA + A_STAGE_BYTES;
        int kofs = ck * 64;
#pragma unroll
        for (int i = 0; i < 8; i++) {
            int idx = tid + i * NTHR;         // 0..1023 (128 rows x 8 col-groups)
            int r = idx >> 3, cc = idx & 7;
            const h16* src = Ah + (size_t)(row0 + r) * HD + kofs + cc * 8;
            cp_async16(sA + swz((unsigned)(r * 128 + cc * 16)), src);
        }
#pragma unroll
        for (int i = 0; i < 8; i++) {
            int idx = tid + i * NTHR;         // 0..1023
            int r = idx >> 3, cc = idx & 7;
            const h16* src = Bp + (size_t)r * KT + kofs + cc * 8;
            cp_async16(sB + swz((unsigned)(r * 128 + cc * 16)), src);
        }
        cp_commit();
    };

    // warp tiling: wm in {0,1} -> 64 rows; wn in {0,1} -> 64 cols
    const int wm = wid & 1, wn = (wid >> 1) & 1;
    unsigned abase[4], amask[4], bbase[4], bmask[4];
    const unsigned aK = (unsigned)((lane >> 4) * 16);        // bytes
    const unsigned bK = (unsigned)(((lane >> 3) & 1) * 16);  // bytes
    {
        int r = wm * 64 + ((lane >> 3) & 1) * 8 + (lane & 7);
#pragma unroll
        for (int mf = 0; mf < 4; mf++) {
            unsigned rb = (unsigned)((r + mf * 16) * 128);
            abase[mf] = rb;
            amask[mf] = (rb >> 3) & 0x70;
        }
        int nr = wn * 64 + (lane >> 4) * 8 + (lane & 7);
#pragma unroll
        for (int fp = 0; fp < 4; fp++) {
            unsigned rb = (unsigned)((nr + fp * 16) * 128);
            bbase[fp] = rb;
            bmask[fp] = (rb >> 3) & 0x70;
        }
    }

    auto compute_chunk = [&](int stage) {
        unsigned sA = sbase + stage * STAGE_BYTES;
        unsigned sB = sA + A_STAGE_BYTES;
#pragma unroll
        for (int ks = 0; ks < 4; ks++) {
            unsigned a[4][4];
#pragma unroll
            for (int mf = 0; mf < 4; mf++) {
                unsigned addr = sA + abase[mf] + (((unsigned)(ks * 32) + aK) ^ amask[mf]);
                ldsm4(addr, a[mf][0], a[mf][1], a[mf][2], a[mf][3]);
            }
            unsigned b[8][2];
#pragma unroll
            for (int fp = 0; fp < 4; fp++) {
                unsigned addr = sB + bbase[fp] + (((unsigned)(ks * 32) + bK) ^ bmask[fp]);
                ldsm4(addr, b[2*fp][0], b[2*fp][1], b[2*fp+1][0], b[2*fp+1][1]);
            }
#pragma unroll
            for (int nf = 0; nf < 8; nf++)
#pragma unroll
                for (int mf = 0; mf < 4; mf++)
                    mma16816(c[nf][mf], a[mf], b[nf]);
        }
    };

    // ---- 3-stage pipeline: one barrier per chunk ----
    load_chunk(0, 0);
    load_chunk(1, 1);
#pragma unroll 1
    for (int ck = 0; ck < NCH; ck++) {
        if (ck + 1 < NCH) cp_wait<1>();   // chunk ck resident
        else              cp_wait<0>();
        __syncthreads();                  // all warps done with compute(ck-1)
        if (ck + 2 < NCH) load_chunk(ck + 2, (ck + 2) % 3);  // reuses stage (ck-1)%3
        compute_chunk(ck % 3);
    }
    __syncthreads();   // all warps done with last compute before P aliases stages

    // ---- prefetch identity term (independent of P) before the smem turnover
    float hold[16];
    if (mode == 1) {
#pragma unroll
        for (int i = 0; i < 16; i++) {
            int idx = tid + i * NTHR;
            if (idx < MV * 16) {
                int r = (idx >> 4) + 1;
                int jg = tn * 16 + (idx & 15);
                hold[i] = __half2float(Ah[(size_t)(row0 + r) * HD + jg]);
            }
        }
    }

    // ---- write accumulators to smem P tile (aliases stage buffers) ----
    float* P = (float*)smem;
    {
        int rbase = wm * 64 + (lane >> 2);
        int cbase = wn * 64 + (lane & 3) * 2;
#pragma unroll
        for (int nf = 0; nf < 8; nf++) {
#pragma unroll
            for (int mf = 0; mf < 4; mf++) {
                int col = cbase + nf * 8;
                int rr = rbase + mf * 16;
                *(float2*)&P[rr * PSTRIDE + col]       = make_float2(c[nf][mf][0], c[nf][mf][1]);
                *(float2*)&P[(rr + 8) * PSTRIDE + col] = make_float2(c[nf][mf][2], c[nf][mf][3]);
            }
        }
    }
    __syncthreads();

    if (mode == 0) {
        for (int idx = tid; idx < MV * BN; idx += NTHR) {
            int r = (idx >> 7) + 1;
            int chl = idx & 127;
            int node = row0 + r - 1;
            if (node >= NN) continue;
            int ch = tn * BN + chl;
            float h = P[r * PSTRIDE + chl] + bias1[ch];
            size_t o = (size_t)t * RPAD * HD + (size_t)(node + 1) * HD + ch;
            Oh[o] = __float2half(h);
        }
    } else {
        const float w0 = g_tw[layer*5+0], w1 = g_tw[layer*5+1], w2 = g_tw[layer*5+2],
                    w3 = g_tw[layer*5+3], w4 = g_tw[layer*5+4];
        const float* bc = g_bcat + (layer*4 + t) * 2048 + tn * BN;
        float accS = 0.f, accM = -3.4e38f;
#pragma unroll
        for (int i = 0; i < 16; i++) {
            int idx = tid + i * NTHR;
            if (idx >= MV * 16) break;
            int r = (idx >> 4) + 1;
            int jc = idx & 15;
            int node = row0 + r - 1;
            if (node >= NN) continue;
            int col = jc * 8;
            const float* Pr = P + r * PSTRIDE;
            float plin = Pr[col + 0];
            float prl  = Pr[col + 1];
            float pc   = Pr[col + 2 - PSTRIDE] + Pr[col + 3] + Pr[col + 4 + PSTRIDE];
            float prc  = Pr[col + 5 - PSTRIDE] + Pr[col + 6] + Pr[col + 7 + PSTRIDE];
            float h = w0 * fmaxf(plin + bc[col + 0], 0.f)
                    + w1 * fmaxf(prl  + bc[col + 1], 0.f)
                    + w2 * fmaxf(pc   + bc[col + 3], 0.f)
                    + w3 * fmaxf(prc  + bc[col + 6], 0.f)
                    + w4 * hold[i];
            if (layer == 0) {
                int jg = tn * 16 + jc;
                size_t o = (size_t)t * RPAD * HD + (size_t)(node + 1) * HD + jg;
                Oh[o] = __float2half(h);
            } else {
                accS += h; accM = fmaxf(accM, h);
            }
        }
        if (layer == 1) {
            __syncthreads();                 // everyone done reading P
            float* R = (float*)smem;         // reuse smem for reduction
            R[tid]        = accS;
            R[NTHR + tid] = accM;
            __syncthreads();
            if (tid < 16) {                  // tid == jc
                float s = 0.f, m = -3.4e38f;
#pragma unroll
                for (int g = 0; g < NTHR / 16; g++) {
                    s += R[g * 16 + tid];
                    m = fmaxf(m, R[NTHR + g * 16 + tid]);
                }
                int ch = tn * 16 + tid;
                atomicAdd(&g_psum[ch], s);
                atomicMaxFloat(&g_pmax[ch], m);
            }
        }
    }
}

// ------------------- final head --------------------------------------------
__global__ void k_agg2(const float* __restrict__ ow, const float* __restrict__ ob,
                       float* __restrict__ out) {
    __shared__ float agg[HD];
    int j = threadIdx.x;
    float s  = g_psum[j];
    float mx = g_pmax[j];
    agg[j] = g_aw[0] * s + g_aw[1] * (s / 32768.f) + g_aw[2] * mx;
    __syncthreads();
    if (j < 64) {
        float acc = ob[j];
        for (int k = 0; k < HD; k++) acc += agg[k] * ow[k * 64 + j];
        out[j] = acc;
    }
}

// ------------------- launcher ----------------------------------------------
extern "C" void kernel_launch(void* const* d_in, const int* in_sizes, int n_in,
                              void* d_out, int out_size) {
    (void)in_sizes; (void)n_in; (void)out_size;
    const float* x          = (const float*)d_in[0];
    const float* lin1_w     = (const float*)d_in[1];
    const float* lin1_b     = (const float*)d_in[2];
    const float* lin_w      = (const float*)d_in[3];
    const float* lin_b      = (const float*)d_in[4];
    const float* rel_lin_w  = (const float*)d_in[5];
    const float* rel_lin_b  = (const float*)d_in[6];
    const float* conv_w     = (const float*)d_in[7];
    const float* conv_b     = (const float*)d_in[8];
    const float* rel_conv_w = (const float*)d_in[9];
    const float* rel_conv_b = (const float*)d_in[10];
    const float* out_w      = (const float*)d_in[11];
    const float* out_b      = (const float*)d_in[12];
    const float* trans_arch = (const float*)d_in[13];
    const float* agg_arch   = (const float*)d_in[14];
    float* out = (float*)d_out;

    cudaFuncSetAttribute(k_gemm, cudaFuncAttributeMaxDynamicSharedMemorySize, SMEM_BYTES);

    k_packx<<<4096, 256>>>(x, lin1_w);
    k_packwl<<<(8 * 2048 * 256 + 255) / 256, 256>>>(lin_w, lin_b, rel_lin_w, rel_lin_b,
                                                    conv_w, conv_b, rel_conv_w, rel_conv_b,
                                                    trans_arch, agg_arch);

    dim3 g1(2, MT, TT), gl(16, MT, TT);
    // lin1: X -> A
    k_gemm<<<g1, NTHR, SMEM_BYTES>>>(0, 1, lin1_b, 0, 0);
    // layer 0: A -> B
    k_gemm<<<gl, NTHR, SMEM_BYTES>>>(1, 2, nullptr, 1, 0);
    // layer 1: B -> (aggregation only; activation stores are dead)
    k_gemm<<<gl, NTHR, SMEM_BYTES>>>(2, 1, nullptr, 1, 1);

    k_agg2<<<1, 256>>>(out_w, out_b, out);
}